// round 9
// baseline (speedup 1.0000x reference)
#include <cuda_runtime.h>
#include <cuda_fp8.h>
#include <cstdint>

// ============================================================================
// Problem dims
// ============================================================================
#define M_DIM 16384
#define N_DIM 2048
#define K_DIM 2048

// ============================================================================
// Scratch — packed fp8 tile layout: 8KB blocks [128 rows x 64B], block id =
// tile*32 + kt. 16B chunks pi-permuted and XOR-swizzled for ldmatrix.
// ============================================================================
__device__ __align__(1024) uint8_t g_xq[(size_t)M_DIM * K_DIM];   // 32 MB
__device__ __align__(1024) uint8_t g_wq[(size_t)N_DIM * K_DIM];   // 4 MB
__device__ unsigned int g_amax[2];   // zero-init; atomicMax idempotent across replays

__device__ __forceinline__ uint32_t swz_off(uint32_t r, uint32_t c) {
    return ((r >> 1) << 7) + (((((r & 1u) << 2) | c) ^ ((r >> 1) & 7u)) << 4);
}
__device__ __forceinline__ float make_scale(unsigned int amax_bits) {
    return 448.0f / (__uint_as_float(amax_bits) + 1e-12f) * 0.9f;
}

// ============================================================================
// Stage 1: fused amax, MLP=8 (8 independent float4 chains = 128B/thread/step)
// ============================================================================
#define AMAX_XBLOCKS 2048
#define AMAX_WBLOCKS 256
#define AMAX_BLOCKS  (AMAX_XBLOCKS + AMAX_WBLOCKS)

__device__ __forceinline__ float fmax4(const float4 v) {
    return fmaxf(fmaxf(fabsf(v.x), fabsf(v.y)), fmaxf(fabsf(v.z), fabsf(v.w)));
}

__global__ void amax_fused_kernel(const float* __restrict__ x, const float* __restrict__ w) {
    const bool isw = (blockIdx.x >= AMAX_XBLOCKS);
    const float* in = isw ? w : x;
    const int slot  = isw ? 1 : 0;
    const int bid   = isw ? (blockIdx.x - AMAX_XBLOCKS) : blockIdx.x;
    const int nblk  = isw ? AMAX_WBLOCKS : AMAX_XBLOCKS;
    const int n4    = (isw ? (N_DIM * K_DIM) : (M_DIM * K_DIM)) / 4;

    float m0 = 0.f, m1 = 0.f, m2 = 0.f, m3 = 0.f, m4 = 0.f, m5 = 0.f, m6 = 0.f, m7 = 0.f;
    const int stride = nblk * blockDim.x;
    // each step: 8 consecutive float4 (128B) per thread, independent loads
    for (int i = bid * blockDim.x + threadIdx.x; i * 8 < n4; i += stride) {
        const float4* p = reinterpret_cast<const float4*>(in) + (size_t)i * 8;
        float4 v0 = p[0], v1 = p[1], v2 = p[2], v3 = p[3];
        float4 v4 = p[4], v5 = p[5], v6 = p[6], v7 = p[7];
        m0 = fmaxf(m0, fmax4(v0)); m1 = fmaxf(m1, fmax4(v1));
        m2 = fmaxf(m2, fmax4(v2)); m3 = fmaxf(m3, fmax4(v3));
        m4 = fmaxf(m4, fmax4(v4)); m5 = fmaxf(m5, fmax4(v5));
        m6 = fmaxf(m6, fmax4(v6)); m7 = fmaxf(m7, fmax4(v7));
    }
    float m = fmaxf(fmaxf(fmaxf(m0, m1), fmaxf(m2, m3)),
                    fmaxf(fmaxf(m4, m5), fmaxf(m6, m7)));
    #pragma unroll
    for (int o = 16; o; o >>= 1) m = fmaxf(m, __shfl_xor_sync(0xffffffffu, m, o));
    if ((threadIdx.x & 31) == 0) atomicMax(&g_amax[slot], __float_as_uint(m));
}

// ============================================================================
// Stage 2: quantize BOTH tensors to e4m3, pi-permute, pack swizzled blocks.
// ============================================================================
__device__ __forceinline__ uint32_t quant4(const float4 v, float s) {
    return  (uint32_t)__nv_cvt_float_to_fp8(v.x * s, __NV_SATFINITE, __NV_E4M3)
         | ((uint32_t)__nv_cvt_float_to_fp8(v.y * s, __NV_SATFINITE, __NV_E4M3) << 8)
         | ((uint32_t)__nv_cvt_float_to_fp8(v.z * s, __NV_SATFINITE, __NV_E4M3) << 16)
         | ((uint32_t)__nv_cvt_float_to_fp8(v.w * s, __NV_SATFINITE, __NV_E4M3) << 24);
}

#define X_CHUNKS ((M_DIM * K_DIM) / 16)
#define ALL_CHUNKS (((M_DIM + N_DIM) * K_DIM) / 16)

__global__ void quant_pack_kernel(const float* __restrict__ x, const float* __restrict__ w) {
    const float sx = make_scale(g_amax[0]);
    const float sw = make_scale(g_amax[1]);
    const int stride = gridDim.x * blockDim.x;
    for (int t = blockIdx.x * blockDim.x + threadIdx.x; t < ALL_CHUNKS; t += stride) {
        const bool isw = (t >= X_CHUNKS);
        const int tt = isw ? (t - X_CHUNKS) : t;
        const float* in = isw ? w : x;
        uint8_t* outq = isw ? g_wq : g_xq;
        const float s = isw ? sw : sx;

        const int m  = tt >> 7;
        const int kc = tt & 127;
        const float4* src = reinterpret_cast<const float4*>(in) + ((size_t)tt << 2);
        const uint32_t qx = quant4(src[0], s);
        const uint32_t qy = quant4(src[1], s);
        const uint32_t qz = quant4(src[2], s);
        const uint32_t qw = quant4(src[3], s);
        uint4 q;                                 // pi permutation
        q.x = (qx & 0xFFFFu) | (qz << 16);
        q.y = (qx >> 16)     | (qz & 0xFFFF0000u);
        q.z = (qy & 0xFFFFu) | (qw << 16);
        q.w = (qy >> 16)     | (qw & 0xFFFF0000u);

        const uint32_t mt = (uint32_t)m >> 7, rm = (uint32_t)m & 127u;
        const uint32_t kt = (uint32_t)kc >> 2, c = (uint32_t)kc & 3u;
        const size_t dst = ((size_t)(mt * 32u + kt) << 13) + swz_off(rm, c);
        *reinterpret_cast<uint4*>(outq + dst) = q;
    }
}

// ============================================================================
// Stage 3: GEMM. fp8 SMEM tiles, ldmatrix + exact cvt -> HMMA m16n8k16.
// CTA tile 128x128, BK=128 (16 iters), 3-stage cp.async.bulk pipeline.
// Inner loop reordered: per i, half-k0 across all j THEN half-k1 across all j
// (spaces dependent same-acc HMMAs 4 issues apart).
// ============================================================================
#define GEMM_THREADS 256
#define K_ITERS (K_DIM / 128)          // 16
#define STAGES 3
#define OP_BYTES 16384
#define STAGE_BYTES (2 * OP_BYTES)
#define SMEM_BYTES (1024 + STAGES * STAGE_BYTES)  // 99328

__device__ __forceinline__ uint32_t smem_u32(const void* p) {
    uint32_t a;
    asm("{ .reg .u64 t; cvta.to.shared.u64 t, %1; cvt.u32.u64 %0, t; }" : "=r"(a) : "l"(p));
    return a;
}

#define MBARRIER_INIT(mbar, count) \
    asm volatile("mbarrier.init.shared.b64 [%0], %1;" :: "r"((uint32_t)(mbar)), "r"((uint32_t)(count)) : "memory")
#define MBARRIER_EXPECT_TX(mbar, bytes) \
    asm volatile("mbarrier.arrive.expect_tx.shared.b64 _, [%0], %1;" :: "r"((uint32_t)(mbar)), "r"((uint32_t)(bytes)) : "memory")
#define MBARRIER_WAIT_PARITY(mbar_smem_addr, phase_parity) do { \
    uint32_t _mbar = (uint32_t)(mbar_smem_addr); \
    uint32_t _parity = (uint32_t)(phase_parity); \
    uint32_t _done; \
    asm volatile("{\n\t.reg .pred p;\n\t" \
        "mbarrier.try_wait.parity.acquire.cta.shared::cta.b64 p, [%1], %2;\n\t" \
        "selp.b32 %0, 1, 0, p;\n\t}" : "=r"(_done) : "r"(_mbar), "r"(_parity) : "memory"); \
    if (!_done) { \
        asm volatile("{\n\t.reg .pred P1;\n\t" \
            "WAIT_LOOP_%=:\n\t" \
            "mbarrier.try_wait.parity.acquire.cta.shared::cta.b64 P1, [%0], %1, 0x989680;\n\t" \
            "@P1 bra.uni WAIT_DONE_%=;\n\t" \
            "bra.uni WAIT_LOOP_%=;\n\t" \
            "WAIT_DONE_%=:\n\t}" :: "r"(_mbar), "r"(_parity) : "memory"); \
    } \
} while(0)

#define BULK_G2S(dst, src, bytes, mbar) \
    asm volatile("cp.async.bulk.shared::cluster.global.mbarrier::complete_tx::bytes [%0], [%1], %2, [%3];" \
        :: "r"((uint32_t)(dst)), "l"(src), "r"((uint32_t)(bytes)), "r"((uint32_t)(mbar)) : "memory")

#define LDSM_X4(r0, r1, r2, r3, addr) \
    asm volatile("ldmatrix.sync.aligned.m8n8.x4.shared.b16 {%0,%1,%2,%3}, [%4];" \
        : "=r"(r0), "=r"(r1), "=r"(r2), "=r"(r3) : "r"(addr))

__device__ __forceinline__ uint32_t cvt_lo(uint32_t p) {
    uint32_t r;
    asm("cvt.rn.f16x2.e4m3x2 %0, %1;" : "=r"(r) : "h"((uint16_t)(p & 0xFFFFu)));
    return r;
}
__device__ __forceinline__ uint32_t cvt_hi(uint32_t p) {
    uint32_t r;
    asm("cvt.rn.f16x2.e4m3x2 %0, %1;" : "=r"(r) : "h"((uint16_t)(p >> 16)));
    return r;
}

__device__ __forceinline__ void hmma(
    float& d0, float& d1, float& d2, float& d3,
    uint32_t a0, uint32_t a1, uint32_t a2, uint32_t a3,
    uint32_t b0, uint32_t b1)
{
    asm volatile(
        "mma.sync.aligned.m16n8k16.row.col.f32.f16.f16.f32 "
        "{%0,%1,%2,%3}, {%4,%5,%6,%7}, {%8,%9}, {%0,%1,%2,%3};"
        : "+f"(d0), "+f"(d1), "+f"(d2), "+f"(d3)
        : "r"(a0), "r"(a1), "r"(a2), "r"(a3), "r"(b0), "r"(b1));
}

__global__ void __launch_bounds__(GEMM_THREADS, 2)
gemm_kernel(const float* __restrict__ bias, float* __restrict__ out) {
    extern __shared__ char smem[];
    const uint32_t sbase = smem_u32(smem);
    const uint32_t stage0 = sbase + 1024;

    const int tid  = threadIdx.x;
    const int wid  = tid >> 5;
    const int lane = tid & 31;
    const int lr   = lane >> 2;
    const int lc   = lane & 3;
    const int wm   = (wid & 1) * 64;
    const int wn   = (wid >> 1) * 32;
    const int m0   = blockIdx.y * 128;
    const int n0   = blockIdx.x * 128;

    const uint8_t* gA = g_xq + ((size_t)blockIdx.y << 18);
    const uint8_t* gB = g_wq + ((size_t)blockIdx.x << 18);

    if (tid == 0) {
        #pragma unroll
        for (int s = 0; s < STAGES; s++) MBARRIER_INIT(sbase + s * 8, 1);
    }
    __syncthreads();

    const uint32_t r8 = lane & 7;
    uint32_t aoff[4], boff[2];
    {
        const uint32_t a_row_add = ((lane >> 3) & 1) * 8;
        const uint32_t a_c       = (uint32_t)(lane >> 4);
        #pragma unroll
        for (int i = 0; i < 4; i++)
            aoff[i] = swz_off((uint32_t)(wm + i * 16) + a_row_add + r8, a_c);
        const uint32_t b_row_add = ((lane >> 4) & 1) * 8;
        const uint32_t b_c       = (uint32_t)((lane >> 3) & 1);
        #pragma unroll
        for (int j2 = 0; j2 < 2; j2++)
            boff[j2] = swz_off((uint32_t)(wn + j2 * 16) + b_row_add + r8, b_c);
    }

    float acc[4][4][4];
    #pragma unroll
    for (int i = 0; i < 4; i++)
        #pragma unroll
        for (int j = 0; j < 4; j++)
            #pragma unroll
            for (int t = 0; t < 4; t++) acc[i][j][t] = 0.0f;

    if (tid == 0) {
        #pragma unroll
        for (int s = 0; s < STAGES - 1; s++) {
            const uint32_t mb = sbase + s * 8;
            const uint32_t dst = stage0 + s * STAGE_BYTES;
            MBARRIER_EXPECT_TX(mb, STAGE_BYTES);
            BULK_G2S(dst, gA + (size_t)s * OP_BYTES, OP_BYTES, mb);
            BULK_G2S(dst + OP_BYTES, gB + (size_t)s * OP_BYTES, OP_BYTES, mb);
        }
    }

    int c_slot = 0, c_phase = 0;
    int p_slot = STAGES - 1;
    for (int it = 0; it < K_ITERS; it++) {
        MBARRIER_WAIT_PARITY(sbase + c_slot * 8, c_phase);
        __syncthreads();

        if (tid == 0 && it + STAGES - 1 < K_ITERS) {
            const int nit = it + STAGES - 1;
            const uint32_t mb = sbase + p_slot * 8;
            const uint32_t dst = stage0 + p_slot * STAGE_BYTES;
            MBARRIER_EXPECT_TX(mb, STAGE_BYTES);
            BULK_G2S(dst, gA + (size_t)nit * OP_BYTES, OP_BYTES, mb);
            BULK_G2S(dst + OP_BYTES, gB + (size_t)nit * OP_BYTES, OP_BYTES, mb);
        }
        if (++p_slot == STAGES) p_slot = 0;

        const uint32_t stg = stage0 + c_slot * STAGE_BYTES;
        if (++c_slot == STAGES) { c_slot = 0; c_phase ^= 1; }

        #pragma unroll
        for (int ks = 0; ks < 4; ks++) {
            const uint32_t blk = (uint32_t)(ks >> 1) * 8192u;
            const uint32_t kx  = (ks & 1) ? 0x20u : 0u;
            const uint32_t aS = stg + blk;
            const uint32_t bS = stg + OP_BYTES + blk;

            uint32_t bp[2][4];
            LDSM_X4(bp[0][0], bp[0][1], bp[0][2], bp[0][3], bS + (boff[0] ^ kx));
            LDSM_X4(bp[1][0], bp[1][1], bp[1][2], bp[1][3], bS + (boff[1] ^ kx));
            uint32_t bf[4][4];
            #pragma unroll
            for (int j = 0; j < 4; j++) {
                const uint32_t p0 = bp[j >> 1][(j & 1) * 2];
                const uint32_t p1 = bp[j >> 1][(j & 1) * 2 + 1];
                bf[j][0] = cvt_lo(p0);  bf[j][1] = cvt_hi(p0);
                bf[j][2] = cvt_lo(p1);  bf[j][3] = cvt_hi(p1);
            }

            #pragma unroll
            for (int i = 0; i < 4; i++) {
                uint32_t a0, a1, a2, a3;
                LDSM_X4(a0, a1, a2, a3, aS + (aoff[i] ^ kx));
                uint32_t af[8];
                af[0] = cvt_lo(a0); af[1] = cvt_lo(a1); af[2] = cvt_hi(a0); af[3] = cvt_hi(a1);
                af[4] = cvt_lo(a2); af[5] = cvt_lo(a3); af[6] = cvt_hi(a2); af[7] = cvt_hi(a3);
                // half-k0 across all j, then half-k1: dependent same-acc HMMAs
                // spaced 4 issues apart instead of back-to-back.
                #pragma unroll
                for (int j = 0; j < 4; j++)
                    hmma(acc[i][j][0], acc[i][j][1], acc[i][j][2], acc[i][j][3],
                         af[0], af[1], af[2], af[3], bf[j][0], bf[j][1]);
                #pragma unroll
                for (int j = 0; j < 4; j++)
                    hmma(acc[i][j][0], acc[i][j][1], acc[i][j][2], acc[i][j][3],
                         af[4], af[5], af[6], af[7], bf[j][2], bf[j][3]);
            }
        }
    }

    // Epilogue: D*inv_scale + bias
    const float inv = 1.0f / (make_scale(g_amax[0]) * make_scale(g_amax[1]));
    #pragma unroll
    for (int i = 0; i < 4; i++) {
        const int rA = m0 + wm + i * 16 + lr;
        const int rB = rA + 8;
        #pragma unroll
        for (int j = 0; j < 4; j++) {
            const int c = n0 + wn + j * 8 + lc * 2;
            const float2 bv = *reinterpret_cast<const float2*>(bias + c);
            float2 o0, o1;
            o0.x = acc[i][j][0] * inv + bv.x;
            o0.y = acc[i][j][1] * inv + bv.y;
            o1.x = acc[i][j][2] * inv + bv.x;
            o1.y = acc[i][j][3] * inv + bv.y;
            *reinterpret_cast<float2*>(out + (size_t)rA * N_DIM + c) = o0;
            *reinterpret_cast<float2*>(out + (size_t)rB * N_DIM + c) = o1;
        }
    }
}

// ============================================================================
// Launcher — 3 launches: amax (fused), quant, gemm.
// ============================================================================
extern "C" void kernel_launch(void* const* d_in, const int* in_sizes, int n_in,
                              void* d_out, int out_size) {
    const float* x = (const float*)d_in[0];   // [4,4096,2048]
    const float* w = (const float*)d_in[1];   // [2048,2048]
    const float* b = (const float*)d_in[2];   // [2048]
    float* out = (float*)d_out;               // [4,4096,2048] fp32

    cudaFuncSetAttribute(gemm_kernel, cudaFuncAttributeMaxDynamicSharedMemorySize, SMEM_BYTES);

    amax_fused_kernel<<<AMAX_BLOCKS, 256>>>(x, w);
    quant_pack_kernel<<<3072, 256>>>(x, w);

    dim3 grid(N_DIM / 128, M_DIM / 128);
    gemm_kernel<<<grid, GEMM_THREADS, SMEM_BYTES>>>(b, out);
}

// round 10
// speedup vs baseline: 1.0806x; 1.0806x over previous
#include <cuda_runtime.h>
#include <cuda_fp8.h>
#include <cstdint>

// ============================================================================
// Problem dims
// ============================================================================
#define M_DIM 16384
#define N_DIM 2048
#define K_DIM 2048

// ============================================================================
// Scratch — packed fp8 tile layout: 8KB blocks [128 rows x 64B], block id =
// tile*32 + kt. 16B chunks pi-permuted and XOR-swizzled for ldmatrix.
// ============================================================================
__device__ __align__(1024) uint8_t g_xq[(size_t)M_DIM * K_DIM];   // 32 MB
__device__ __align__(1024) uint8_t g_wq[(size_t)N_DIM * K_DIM];   // 4 MB
__device__ unsigned int g_amax[2];   // zero-init; atomicMax idempotent across replays

__device__ __forceinline__ uint32_t swz_off(uint32_t r, uint32_t c) {
    return ((r >> 1) << 7) + (((((r & 1u) << 2) | c) ^ ((r >> 1) & 7u)) << 4);
}
__device__ __forceinline__ float make_scale(unsigned int amax_bits) {
    return 448.0f / (__uint_as_float(amax_bits) + 1e-12f) * 0.9f;
}

// ============================================================================
// Stage 1: fused amax — exact coverage: every thread does exactly 2 iters of
// 4 independent float4 (64B), 4 independent max chains. No idle threads.
// ============================================================================
#define AMAX_XBLOCKS 1024
#define AMAX_WBLOCKS 128
#define AMAX_BLOCKS  (AMAX_XBLOCKS + AMAX_WBLOCKS)
#define AMAX_ITERS   2

__device__ __forceinline__ float fmax4(const float4 v) {
    return fmaxf(fmaxf(fabsf(v.x), fabsf(v.y)), fmaxf(fabsf(v.z), fabsf(v.w)));
}

__global__ void amax_fused_kernel(const float* __restrict__ x, const float* __restrict__ w) {
    const bool isw = (blockIdx.x >= AMAX_XBLOCKS);
    const float* in = isw ? w : x;
    const int slot  = isw ? 1 : 0;
    const int bid   = isw ? (blockIdx.x - AMAX_XBLOCKS) : blockIdx.x;
    const int nblk  = isw ? AMAX_WBLOCKS : AMAX_XBLOCKS;
    const int stride = nblk * 256;   // step-index stride (each step = 4 float4)

    float m0 = 0.f, m1 = 0.f, m2 = 0.f, m3 = 0.f;
    int i = bid * 256 + threadIdx.x;
    #pragma unroll
    for (int s = 0; s < AMAX_ITERS; s++, i += stride) {
        const float4* p = reinterpret_cast<const float4*>(in) + (size_t)i * 4;
        float4 v0 = p[0], v1 = p[1], v2 = p[2], v3 = p[3];
        m0 = fmaxf(m0, fmax4(v0));
        m1 = fmaxf(m1, fmax4(v1));
        m2 = fmaxf(m2, fmax4(v2));
        m3 = fmaxf(m3, fmax4(v3));
    }
    float m = fmaxf(fmaxf(m0, m1), fmaxf(m2, m3));
    #pragma unroll
    for (int o = 16; o; o >>= 1) m = fmaxf(m, __shfl_xor_sync(0xffffffffu, m, o));
    if ((threadIdx.x & 31) == 0) atomicMax(&g_amax[slot], __float_as_uint(m));
}

// ============================================================================
// Stage 2: quantize BOTH tensors to e4m3, pi-permute, pack swizzled blocks.
// ============================================================================
__device__ __forceinline__ uint32_t quant4(const float4 v, float s) {
    return  (uint32_t)__nv_cvt_float_to_fp8(v.x * s, __NV_SATFINITE, __NV_E4M3)
         | ((uint32_t)__nv_cvt_float_to_fp8(v.y * s, __NV_SATFINITE, __NV_E4M3) << 8)
         | ((uint32_t)__nv_cvt_float_to_fp8(v.z * s, __NV_SATFINITE, __NV_E4M3) << 16)
         | ((uint32_t)__nv_cvt_float_to_fp8(v.w * s, __NV_SATFINITE, __NV_E4M3) << 24);
}

#define X_CHUNKS ((M_DIM * K_DIM) / 16)
#define ALL_CHUNKS (((M_DIM + N_DIM) * K_DIM) / 16)

__global__ void quant_pack_kernel(const float* __restrict__ x, const float* __restrict__ w) {
    const float sx = make_scale(g_amax[0]);
    const float sw = make_scale(g_amax[1]);
    const int stride = gridDim.x * blockDim.x;
    for (int t = blockIdx.x * blockDim.x + threadIdx.x; t < ALL_CHUNKS; t += stride) {
        const bool isw = (t >= X_CHUNKS);
        const int tt = isw ? (t - X_CHUNKS) : t;
        const float* in = isw ? w : x;
        uint8_t* outq = isw ? g_wq : g_xq;
        const float s = isw ? sw : sx;

        const int m  = tt >> 7;
        const int kc = tt & 127;
        const float4* src = reinterpret_cast<const float4*>(in) + ((size_t)tt << 2);
        const uint32_t qx = quant4(src[0], s);
        const uint32_t qy = quant4(src[1], s);
        const uint32_t qz = quant4(src[2], s);
        const uint32_t qw = quant4(src[3], s);
        uint4 q;                                 // pi permutation
        q.x = (qx & 0xFFFFu) | (qz << 16);
        q.y = (qx >> 16)     | (qz & 0xFFFF0000u);
        q.z = (qy & 0xFFFFu) | (qw << 16);
        q.w = (qy >> 16)     | (qw & 0xFFFF0000u);

        const uint32_t mt = (uint32_t)m >> 7, rm = (uint32_t)m & 127u;
        const uint32_t kt = (uint32_t)kc >> 2, c = (uint32_t)kc & 3u;
        const size_t dst = ((size_t)(mt * 32u + kt) << 13) + swz_off(rm, c);
        *reinterpret_cast<uint4*>(outq + dst) = q;
    }
}

// ============================================================================
// Stage 3: GEMM (R8-proven). fp8 SMEM tiles, ldmatrix + exact cvt -> HMMA.
// CTA tile 128x128, BK=128 (16 iters), 3-stage cp.async.bulk pipeline.
// At ~97% of the legacy quarter-rate mma.sync ceiling on this die.
// ============================================================================
#define GEMM_THREADS 256
#define K_ITERS (K_DIM / 128)          // 16
#define STAGES 3
#define OP_BYTES 16384
#define STAGE_BYTES (2 * OP_BYTES)
#define SMEM_BYTES (1024 + STAGES * STAGE_BYTES)  // 99328

__device__ __forceinline__ uint32_t smem_u32(const void* p) {
    uint32_t a;
    asm("{ .reg .u64 t; cvta.to.shared.u64 t, %1; cvt.u32.u64 %0, t; }" : "=r"(a) : "l"(p));
    return a;
}

#define MBARRIER_INIT(mbar, count) \
    asm volatile("mbarrier.init.shared.b64 [%0], %1;" :: "r"((uint32_t)(mbar)), "r"((uint32_t)(count)) : "memory")
#define MBARRIER_EXPECT_TX(mbar, bytes) \
    asm volatile("mbarrier.arrive.expect_tx.shared.b64 _, [%0], %1;" :: "r"((uint32_t)(mbar)), "r"((uint32_t)(bytes)) : "memory")
#define MBARRIER_WAIT_PARITY(mbar_smem_addr, phase_parity) do { \
    uint32_t _mbar = (uint32_t)(mbar_smem_addr); \
    uint32_t _parity = (uint32_t)(phase_parity); \
    uint32_t _done; \
    asm volatile("{\n\t.reg .pred p;\n\t" \
        "mbarrier.try_wait.parity.acquire.cta.shared::cta.b64 p, [%1], %2;\n\t" \
        "selp.b32 %0, 1, 0, p;\n\t}" : "=r"(_done) : "r"(_mbar), "r"(_parity) : "memory"); \
    if (!_done) { \
        asm volatile("{\n\t.reg .pred P1;\n\t" \
            "WAIT_LOOP_%=:\n\t" \
            "mbarrier.try_wait.parity.acquire.cta.shared::cta.b64 P1, [%0], %1, 0x989680;\n\t" \
            "@P1 bra.uni WAIT_DONE_%=;\n\t" \
            "bra.uni WAIT_LOOP_%=;\n\t" \
            "WAIT_DONE_%=:\n\t}" :: "r"(_mbar), "r"(_parity) : "memory"); \
    } \
} while(0)

#define BULK_G2S(dst, src, bytes, mbar) \
    asm volatile("cp.async.bulk.shared::cluster.global.mbarrier::complete_tx::bytes [%0], [%1], %2, [%3];" \
        :: "r"((uint32_t)(dst)), "l"(src), "r"((uint32_t)(bytes)), "r"((uint32_t)(mbar)) : "memory")

#define LDSM_X4(r0, r1, r2, r3, addr) \
    asm volatile("ldmatrix.sync.aligned.m8n8.x4.shared.b16 {%0,%1,%2,%3}, [%4];" \
        : "=r"(r0), "=r"(r1), "=r"(r2), "=r"(r3) : "r"(addr))

__device__ __forceinline__ uint32_t cvt_lo(uint32_t p) {
    uint32_t r;
    asm("cvt.rn.f16x2.e4m3x2 %0, %1;" : "=r"(r) : "h"((uint16_t)(p & 0xFFFFu)));
    return r;
}
__device__ __forceinline__ uint32_t cvt_hi(uint32_t p) {
    uint32_t r;
    asm("cvt.rn.f16x2.e4m3x2 %0, %1;" : "=r"(r) : "h"((uint16_t)(p >> 16)));
    return r;
}

__device__ __forceinline__ void hmma(
    float& d0, float& d1, float& d2, float& d3,
    uint32_t a0, uint32_t a1, uint32_t a2, uint32_t a3,
    uint32_t b0, uint32_t b1)
{
    asm volatile(
        "mma.sync.aligned.m16n8k16.row.col.f32.f16.f16.f32 "
        "{%0,%1,%2,%3}, {%4,%5,%6,%7}, {%8,%9}, {%0,%1,%2,%3};"
        : "+f"(d0), "+f"(d1), "+f"(d2), "+f"(d3)
        : "r"(a0), "r"(a1), "r"(a2), "r"(a3), "r"(b0), "r"(b1));
}

__global__ void __launch_bounds__(GEMM_THREADS, 2)
gemm_kernel(const float* __restrict__ bias, float* __restrict__ out) {
    extern __shared__ char smem[];
    const uint32_t sbase = smem_u32(smem);
    const uint32_t stage0 = sbase + 1024;

    const int tid  = threadIdx.x;
    const int wid  = tid >> 5;
    const int lane = tid & 31;
    const int lr   = lane >> 2;
    const int lc   = lane & 3;
    const int wm   = (wid & 1) * 64;
    const int wn   = (wid >> 1) * 32;
    const int m0   = blockIdx.y * 128;
    const int n0   = blockIdx.x * 128;

    const uint8_t* gA = g_xq + ((size_t)blockIdx.y << 18);
    const uint8_t* gB = g_wq + ((size_t)blockIdx.x << 18);

    if (tid == 0) {
        #pragma unroll
        for (int s = 0; s < STAGES; s++) MBARRIER_INIT(sbase + s * 8, 1);
    }
    __syncthreads();

    const uint32_t r8 = lane & 7;
    uint32_t aoff[4], boff[2];
    {
        const uint32_t a_row_add = ((lane >> 3) & 1) * 8;
        const uint32_t a_c       = (uint32_t)(lane >> 4);
        #pragma unroll
        for (int i = 0; i < 4; i++)
            aoff[i] = swz_off((uint32_t)(wm + i * 16) + a_row_add + r8, a_c);
        const uint32_t b_row_add = ((lane >> 4) & 1) * 8;
        const uint32_t b_c       = (uint32_t)((lane >> 3) & 1);
        #pragma unroll
        for (int j2 = 0; j2 < 2; j2++)
            boff[j2] = swz_off((uint32_t)(wn + j2 * 16) + b_row_add + r8, b_c);
    }

    float acc[4][4][4];
    #pragma unroll
    for (int i = 0; i < 4; i++)
        #pragma unroll
        for (int j = 0; j < 4; j++)
            #pragma unroll
            for (int t = 0; t < 4; t++) acc[i][j][t] = 0.0f;

    if (tid == 0) {
        #pragma unroll
        for (int s = 0; s < STAGES - 1; s++) {
            const uint32_t mb = sbase + s * 8;
            const uint32_t dst = stage0 + s * STAGE_BYTES;
            MBARRIER_EXPECT_TX(mb, STAGE_BYTES);
            BULK_G2S(dst, gA + (size_t)s * OP_BYTES, OP_BYTES, mb);
            BULK_G2S(dst + OP_BYTES, gB + (size_t)s * OP_BYTES, OP_BYTES, mb);
        }
    }

    int c_slot = 0, c_phase = 0;
    int p_slot = STAGES - 1;
    for (int it = 0; it < K_ITERS; it++) {
        MBARRIER_WAIT_PARITY(sbase + c_slot * 8, c_phase);
        __syncthreads();

        if (tid == 0 && it + STAGES - 1 < K_ITERS) {
            const int nit = it + STAGES - 1;
            const uint32_t mb = sbase + p_slot * 8;
            const uint32_t dst = stage0 + p_slot * STAGE_BYTES;
            MBARRIER_EXPECT_TX(mb, STAGE_BYTES);
            BULK_G2S(dst, gA + (size_t)nit * OP_BYTES, OP_BYTES, mb);
            BULK_G2S(dst + OP_BYTES, gB + (size_t)nit * OP_BYTES, OP_BYTES, mb);
        }
        if (++p_slot == STAGES) p_slot = 0;

        const uint32_t stg = stage0 + c_slot * STAGE_BYTES;
        if (++c_slot == STAGES) { c_slot = 0; c_phase ^= 1; }

        #pragma unroll
        for (int ks = 0; ks < 4; ks++) {
            const uint32_t blk = (uint32_t)(ks >> 1) * 8192u;
            const uint32_t kx  = (ks & 1) ? 0x20u : 0u;
            const uint32_t aS = stg + blk;
            const uint32_t bS = stg + OP_BYTES + blk;

            uint32_t bp[2][4];
            LDSM_X4(bp[0][0], bp[0][1], bp[0][2], bp[0][3], bS + (boff[0] ^ kx));
            LDSM_X4(bp[1][0], bp[1][1], bp[1][2], bp[1][3], bS + (boff[1] ^ kx));
            uint32_t bf[4][4];
            #pragma unroll
            for (int j = 0; j < 4; j++) {
                const uint32_t p0 = bp[j >> 1][(j & 1) * 2];
                const uint32_t p1 = bp[j >> 1][(j & 1) * 2 + 1];
                bf[j][0] = cvt_lo(p0);  bf[j][1] = cvt_hi(p0);
                bf[j][2] = cvt_lo(p1);  bf[j][3] = cvt_hi(p1);
            }

            #pragma unroll
            for (int i = 0; i < 4; i++) {
                uint32_t a0, a1, a2, a3;
                LDSM_X4(a0, a1, a2, a3, aS + (aoff[i] ^ kx));
                uint32_t af[8];
                af[0] = cvt_lo(a0); af[1] = cvt_lo(a1); af[2] = cvt_hi(a0); af[3] = cvt_hi(a1);
                af[4] = cvt_lo(a2); af[5] = cvt_lo(a3); af[6] = cvt_hi(a2); af[7] = cvt_hi(a3);
                #pragma unroll
                for (int j = 0; j < 4; j++) {
                    hmma(acc[i][j][0], acc[i][j][1], acc[i][j][2], acc[i][j][3],
                         af[0], af[1], af[2], af[3], bf[j][0], bf[j][1]);
                    hmma(acc[i][j][0], acc[i][j][1], acc[i][j][2], acc[i][j][3],
                         af[4], af[5], af[6], af[7], bf[j][2], bf[j][3]);
                }
            }
        }
    }

    // Epilogue: D*inv_scale + bias
    const float inv = 1.0f / (make_scale(g_amax[0]) * make_scale(g_amax[1]));
    #pragma unroll
    for (int i = 0; i < 4; i++) {
        const int rA = m0 + wm + i * 16 + lr;
        const int rB = rA + 8;
        #pragma unroll
        for (int j = 0; j < 4; j++) {
            const int c = n0 + wn + j * 8 + lc * 2;
            const float2 bv = *reinterpret_cast<const float2*>(bias + c);
            float2 o0, o1;
            o0.x = acc[i][j][0] * inv + bv.x;
            o0.y = acc[i][j][1] * inv + bv.y;
            o1.x = acc[i][j][2] * inv + bv.x;
            o1.y = acc[i][j][3] * inv + bv.y;
            *reinterpret_cast<float2*>(out + (size_t)rA * N_DIM + c) = o0;
            *reinterpret_cast<float2*>(out + (size_t)rB * N_DIM + c) = o1;
        }
    }
}

// ============================================================================
// Launcher — 3 launches: amax (fused), quant, gemm.
// ============================================================================
extern "C" void kernel_launch(void* const* d_in, const int* in_sizes, int n_in,
                              void* d_out, int out_size) {
    const float* x = (const float*)d_in[0];   // [4,4096,2048]
    const float* w = (const float*)d_in[1];   // [2048,2048]
    const float* b = (const float*)d_in[2];   // [2048]
    float* out = (float*)d_out;               // [4,4096,2048] fp32

    cudaFuncSetAttribute(gemm_kernel, cudaFuncAttributeMaxDynamicSharedMemorySize, SMEM_BYTES);

    amax_fused_kernel<<<AMAX_BLOCKS, 256>>>(x, w);
    quant_pack_kernel<<<4608, 256>>>(x, w);

    dim3 grid(N_DIM / 128, M_DIM / 128);
    gemm_kernel<<<grid, GEMM_THREADS, SMEM_BYTES>>>(b, out);
}